// round 8
// baseline (speedup 1.0000x reference)
#include <cuda_runtime.h>
#include <math.h>

#define DIM   4096
#define NH    32
#define HD    128
#define SEQ   4096
#define BATCH 16

typedef unsigned long long u64;

// Scratch (allocation-free)
__device__ float g_q  [BATCH * DIM];
__device__ float g_kn [BATCH * DIM];
__device__ float g_vn [BATCH * DIM];
__device__ float g_att[BATCH * DIM];

// ---------------- packed fp32x2 helpers ----------------
__device__ __forceinline__ u64 ffma2(u64 a, u64 b, u64 c) {
    u64 d; asm("fma.rn.f32x2 %0, %1, %2, %3;" : "=l"(d) : "l"(a), "l"(b), "l"(c)); return d;
}
__device__ __forceinline__ void unpack2(u64 v, float& lo, float& hi) {
    asm("mov.b64 {%0, %1}, %2;" : "=f"(lo), "=f"(hi) : "l"(v));
}

#define ROW_U2 (DIM / 4)   // ulonglong2 (16B) elements per 4096-float row

// ---------------------------------------------------------------------------
// Skinny GEMM: out[b][j] = dot(x[b,:], W[j,:]).
// Warp tile: 4 W rows x 4 batches (acc = 32 regs) -> ~80 regs/thread ->
// 3 blocks/SM = 24 warps/SM for latency hiding. W double-buffered in regs.
// Block: 8 warps = 2 row-groups x 4 batch-groups (8 rows x 16 batches).
// The 4 batch-group warps share W rows within the block -> 1 DRAM fetch.
// ---------------------------------------------------------------------------
__device__ __forceinline__ void gemm_warp(const float* __restrict__ x,
                                          const float* __restrict__ Wrows,
                                          float* __restrict__ out,
                                          int j0, int bg /* 0,4,8,12 */) {
    int lane = threadIdx.x & 31;

    u64 acc[4][4];
#pragma unroll
    for (int r = 0; r < 4; r++)
#pragma unroll
        for (int b = 0; b < 4; b++) acc[r][b] = 0ull;

    const ulonglong2* W2 = reinterpret_cast<const ulonglong2*>(Wrows);
    const ulonglong2* X2 = reinterpret_cast<const ulonglong2*>(x) + (size_t)bg * ROW_U2;

    // prologue: W chunk 0
    ulonglong2 w0 = __ldcs(W2 + 0 * ROW_U2 + lane);
    ulonglong2 w1 = __ldcs(W2 + 1 * ROW_U2 + lane);
    ulonglong2 w2 = __ldcs(W2 + 2 * ROW_U2 + lane);
    ulonglong2 w3 = __ldcs(W2 + 3 * ROW_U2 + lane);

#pragma unroll 1
    for (int kb = 0; kb < DIM / 128; kb++) {
        int fidx = kb * 32 + lane;

        ulonglong2 x0 = X2[0 * ROW_U2 + fidx];
        ulonglong2 x1 = X2[1 * ROW_U2 + fidx];
        ulonglong2 x2 = X2[2 * ROW_U2 + fidx];
        ulonglong2 x3 = X2[3 * ROW_U2 + fidx];

        // prefetch next W chunk (register double-buffer)
        ulonglong2 nw0, nw1, nw2, nw3;
        if (kb < DIM / 128 - 1) {
            int nidx = fidx + 32;
            nw0 = __ldcs(W2 + 0 * ROW_U2 + nidx);
            nw1 = __ldcs(W2 + 1 * ROW_U2 + nidx);
            nw2 = __ldcs(W2 + 2 * ROW_U2 + nidx);
            nw3 = __ldcs(W2 + 3 * ROW_U2 + nidx);
        }

#pragma unroll
        for (int b = 0; b < 4; b++) {
            ulonglong2 xv = (b == 0) ? x0 : (b == 1) ? x1 : (b == 2) ? x2 : x3;
            acc[0][b] = ffma2(w0.x, xv.x, acc[0][b]);
            acc[0][b] = ffma2(w0.y, xv.y, acc[0][b]);
            acc[1][b] = ffma2(w1.x, xv.x, acc[1][b]);
            acc[1][b] = ffma2(w1.y, xv.y, acc[1][b]);
            acc[2][b] = ffma2(w2.x, xv.x, acc[2][b]);
            acc[2][b] = ffma2(w2.y, xv.y, acc[2][b]);
            acc[3][b] = ffma2(w3.x, xv.x, acc[3][b]);
            acc[3][b] = ffma2(w3.y, xv.y, acc[3][b]);
        }

        w0 = nw0; w1 = nw1; w2 = nw2; w3 = nw3;
    }

    // collapse k-pairs, butterfly over lanes, lane0 writes
#pragma unroll
    for (int r = 0; r < 4; r++)
#pragma unroll
        for (int b = 0; b < 4; b++) {
            float lo, hi;
            unpack2(acc[r][b], lo, hi);
            float v = lo + hi;
#pragma unroll
            for (int off = 16; off; off >>= 1)
                v += __shfl_xor_sync(0xffffffffu, v, off);
            if (lane == 0)
                out[(size_t)(bg + b) * DIM + j0 + r] = v;
        }
}

// QKV: 1536 blocks x 256 threads. Block = 8 consecutive fused rows
// (2 row-groups x 4 batch-group warps). Blocks never straddle a matrix.
__global__ void __launch_bounds__(256, 3) qkv_gemm(const float* __restrict__ x,
                                                   const float* __restrict__ wq,
                                                   const float* __restrict__ wk,
                                                   const float* __restrict__ wv) {
    int w  = threadIdx.x >> 5;
    int jg = blockIdx.x * 8 + (w >> 2) * 4;
    int bg = (w & 3) * 4;
    int which = jg >> 12;
    int jl    = jg & (DIM - 1);
    const float* W   = (which == 0) ? wq  : (which == 1) ? wk   : wv;
    float*       out = (which == 0) ? g_q : (which == 1) ? g_kn : g_vn;
    gemm_warp(x, W + (size_t)jl * DIM, out, jl, bg);
}

// O projection: 512 blocks x 256 threads, consumes g_att (native layout).
__global__ void __launch_bounds__(256, 3) oproj_gemm(const float* __restrict__ wo,
                                                     float* __restrict__ out) {
    int w  = threadIdx.x >> 5;
    int j  = blockIdx.x * 8 + (w >> 2) * 4;
    int bg = (w & 3) * 4;
    gemm_warp(g_att, wo + (size_t)j * DIM, out, j, bg);
}

// ---------------------------------------------------------------------------
// Decode attention (round-6 form — ~6.1 TB/s already).
// One block per (b,h): 512 blocks, 8 warps, 2-row unroll, streaming loads.
// ---------------------------------------------------------------------------
__global__ void __launch_bounds__(256) decode_attn(const float* __restrict__ kc,
                                                   const float* __restrict__ vc) {
    int bh   = blockIdx.x;
    int b    = bh >> 5;
    int h    = bh & 31;
    int tid  = threadIdx.x;
    int w    = tid >> 5;
    int lane = tid & 31;

    const float4* K = reinterpret_cast<const float4*>(kc + (size_t)bh * SEQ * HD);
    const float4* V = reinterpret_cast<const float4*>(vc + (size_t)bh * SEQ * HD);

    float4 q4 = reinterpret_cast<const float4*>(g_q + b * DIM + h * HD)[lane];
    const float scale = 0.08838834764831845f;   // 1/sqrt(128)

    float  m = -INFINITY;
    float  l = 0.f;
    float4 o = make_float4(0.f, 0.f, 0.f, 0.f);

    for (int i = 0; i < SEQ / 16; i++) {
        int r1 = i * 16 + w;
        int r2 = r1 + 8;
        float4 k1 = __ldcs(K + (size_t)r1 * (HD / 4) + lane);
        float4 v1 = __ldcs(V + (size_t)r1 * (HD / 4) + lane);
        float4 k2 = __ldcs(K + (size_t)r2 * (HD / 4) + lane);
        float4 v2 = __ldcs(V + (size_t)r2 * (HD / 4) + lane);

        float s1 = q4.x * k1.x + q4.y * k1.y + q4.z * k1.z + q4.w * k1.w;
        float s2 = q4.x * k2.x + q4.y * k2.y + q4.z * k2.z + q4.w * k2.w;
#pragma unroll
        for (int off = 16; off; off >>= 1) {
            s1 += __shfl_xor_sync(0xffffffffu, s1, off);
            s2 += __shfl_xor_sync(0xffffffffu, s2, off);
        }
        s1 *= scale;
        s2 *= scale;

        float nm = fmaxf(m, fmaxf(s1, s2));
        float c  = __expf(m - nm);
        float p1 = __expf(s1 - nm);
        float p2 = __expf(s2 - nm);
        l   = l * c + p1 + p2;
        o.x = o.x * c + p1 * v1.x + p2 * v2.x;
        o.y = o.y * c + p1 * v1.y + p2 * v2.y;
        o.z = o.z * c + p1 * v1.z + p2 * v2.z;
        o.w = o.w * c + p1 * v1.w + p2 * v2.w;
        m   = nm;
    }

    // new token (row 4096) handled by warp 0
    if (w == 0) {
        const float4* Kn = reinterpret_cast<const float4*>(g_kn + b * DIM + h * HD);
        const float4* Vn = reinterpret_cast<const float4*>(g_vn + b * DIM + h * HD);
        float4 kv = Kn[lane];
        float4 vv = Vn[lane];
        float s = q4.x * kv.x + q4.y * kv.y + q4.z * kv.z + q4.w * kv.w;
#pragma unroll
        for (int off = 16; off; off >>= 1)
            s += __shfl_xor_sync(0xffffffffu, s, off);
        s *= scale;
        float nm = fmaxf(m, s);
        float c  = __expf(m - nm);
        float p  = __expf(s - nm);
        l   = l * c + p;
        o.x = o.x * c + p * vv.x;
        o.y = o.y * c + p * vv.y;
        o.z = o.z * c + p * vv.z;
        o.w = o.w * c + p * vv.w;
        m   = nm;
    }

    // merge 8 warp-partials
    __shared__ float  sm[8];
    __shared__ float  sl[8];
    __shared__ float4 so[8][32];
    so[w][lane] = o;
    if (lane == 0) { sm[w] = m; sl[w] = l; }
    __syncthreads();

    if (tid < HD) {
        int d = tid;
        float gm = sm[0];
#pragma unroll
        for (int i = 1; i < 8; i++) gm = fmaxf(gm, sm[i]);
        const float* sof = reinterpret_cast<const float*>(so);
        float num = 0.f, den = 0.f;
#pragma unroll
        for (int i = 0; i < 8; i++) {
            float f = __expf(sm[i] - gm);
            num += f * sof[i * HD + d];
            den += f * sl[i];
        }
        g_att[b * DIM + h * HD + d] = num / den;
    }
}

// ---------------------------------------------------------------------------
extern "C" void kernel_launch(void* const* d_in, const int* in_sizes, int n_in,
                              void* d_out, int out_size) {
    const float* x  = (const float*)d_in[0];
    const float* kc = (const float*)d_in[1];
    const float* vc = (const float*)d_in[2];
    const float* wq = (const float*)d_in[3];
    const float* wk = (const float*)d_in[4];
    const float* wv = (const float*)d_in[5];
    const float* wo = (const float*)d_in[6];
    float* out = (float*)d_out;

    qkv_gemm  <<<3 * DIM / 8, 256>>>(x, wq, wk, wv);
    decode_attn<<<BATCH * NH, 256>>>(kc, vc);
    oproj_gemm<<<DIM / 8, 256>>>(wo, out);
}

// round 9
// speedup vs baseline: 1.1876x; 1.1876x over previous
#include <cuda_runtime.h>
#include <math.h>
#include <stdint.h>

#define DIM   4096
#define NH    32
#define HD    128
#define SEQ   4096
#define BATCH 16

#define STAGES 4
#define KCH    128          // k floats per stage
#define BROWS  16           // W rows per block

typedef unsigned long long u64;

// Scratch (allocation-free)
__device__ float g_q  [BATCH * DIM];
__device__ float g_kn [BATCH * DIM];
__device__ float g_vn [BATCH * DIM];
__device__ float g_att[BATCH * DIM];

// ---------------- packed fp32x2 helpers ----------------
__device__ __forceinline__ u64 ffma2(u64 a, u64 b, u64 c) {
    u64 d; asm("fma.rn.f32x2 %0, %1, %2, %3;" : "=l"(d) : "l"(a), "l"(b), "l"(c)); return d;
}
__device__ __forceinline__ void unpack2(u64 v, float& lo, float& hi) {
    asm("mov.b64 {%0, %1}, %2;" : "=f"(lo), "=f"(hi) : "l"(v));
}
__device__ __forceinline__ void cp_async16(uint32_t dst, const void* src) {
    asm volatile("cp.async.cg.shared.global [%0], [%1], 16;" :: "r"(dst), "l"(src));
}

#define ROW_U2 (DIM / 4)   // ulonglong2 (16B) elements per 4096-float row

// ---------------------------------------------------------------------------
// Skinny GEMM with cp.async W pipeline.
// Block: 16 W rows x 16 batches, 8 warps. Warp: 4 rows x 8 batches.
// W streams through a 4-stage smem pipeline (loads never block a warp);
// x is read via LDG (L2-resident, 4x intra-block reuse hits L1).
// ---------------------------------------------------------------------------
__device__ __forceinline__ void gemm_block(const float* __restrict__ x,
                                           const float* __restrict__ Wblk, // 16 rows
                                           float* __restrict__ out,
                                           int j0) {
    __shared__ float sW[STAGES][BROWS][KCH];   // 32 KB

    int tid  = threadIdx.x;
    int w    = tid >> 5;
    int lane = tid & 31;
    int rg   = (w >> 1) * 4;       // row-group base (0,4,8,12)
    int bg   = (w & 1) * 8;        // batch-group base (0 or 8)

    uint32_t sbase = (uint32_t)__cvta_generic_to_shared(&sW[0][0][0]);

    const ulonglong2* X2 = reinterpret_cast<const ulonglong2*>(x);

    u64 acc[4][8];
#pragma unroll
    for (int r = 0; r < 4; r++)
#pragma unroll
        for (int b = 0; b < 8; b++) acc[r][b] = 0ull;

    // ---- stage loader: 8KB = 512 x 16B chunks, 2 per thread ----
    auto load_stage = [&](int s, int kb) {
        int c = tid * 2;
#pragma unroll
        for (int i = 0; i < 2; i++, c++) {
            int row = c >> 5;           // 32 chunks (512B) per row
            int kc  = c & 31;
            uint32_t dst = sbase + (uint32_t)(((s * BROWS + row) * KCH + kc * 4) * 4);
            const float* src = Wblk + (size_t)row * DIM + kb * KCH + kc * 4;
            cp_async16(dst, src);
        }
        asm volatile("cp.async.commit_group;");
    };

    // prologue: fill 3 stages
    load_stage(0, 0);
    load_stage(1, 1);
    load_stage(2, 2);

#pragma unroll 1
    for (int kb = 0; kb < DIM / KCH; kb++) {
        asm volatile("cp.async.wait_group 2;");
        __syncthreads();

        int s = kb & (STAGES - 1);

        // x loads for this stage (L2/L1) — issued first, consumed below
        ulonglong2 xv[8];
#pragma unroll
        for (int b = 0; b < 8; b++)
            xv[b] = X2[(size_t)(bg + b) * ROW_U2 + kb * (KCH / 4) + lane];

        // W from smem (always resident)
        ulonglong2 wv[4];
#pragma unroll
        for (int r = 0; r < 4; r++)
            wv[r] = *reinterpret_cast<const ulonglong2*>(&sW[s][rg + r][lane * 4]);

#pragma unroll
        for (int b = 0; b < 8; b++) {
#pragma unroll
            for (int r = 0; r < 4; r++) {
                acc[r][b] = ffma2(wv[r].x, xv[b].x, acc[r][b]);
                acc[r][b] = ffma2(wv[r].y, xv[b].y, acc[r][b]);
            }
        }

        if (kb + 3 < DIM / KCH) load_stage((kb + 3) & (STAGES - 1), kb + 3);
    }

    // collapse k-pairs, butterfly over lanes, lane0 writes
#pragma unroll
    for (int r = 0; r < 4; r++)
#pragma unroll
        for (int b = 0; b < 8; b++) {
            float lo, hi;
            unpack2(acc[r][b], lo, hi);
            float v = lo + hi;
#pragma unroll
            for (int off = 16; off; off >>= 1)
                v += __shfl_xor_sync(0xffffffffu, v, off);
            if (lane == 0)
                out[(size_t)(bg + b) * DIM + j0 + rg + r] = v;
        }
}

// QKV: 768 blocks x 256 threads. Block = 16 consecutive fused rows.
__global__ void __launch_bounds__(256, 2) qkv_gemm(const float* __restrict__ x,
                                                   const float* __restrict__ wq,
                                                   const float* __restrict__ wk,
                                                   const float* __restrict__ wv) {
    int jg    = blockIdx.x * BROWS;
    int which = jg >> 12;
    int jl    = jg & (DIM - 1);
    const float* W   = (which == 0) ? wq  : (which == 1) ? wk   : wv;
    float*       out = (which == 0) ? g_q : (which == 1) ? g_kn : g_vn;
    gemm_block(x, W + (size_t)jl * DIM, out, jl);
}

// O projection: 256 blocks x 256 threads.
__global__ void __launch_bounds__(256, 2) oproj_gemm(const float* __restrict__ wo,
                                                     float* __restrict__ out) {
    int j = blockIdx.x * BROWS;
    gemm_block(g_att, wo + (size_t)j * DIM, out, j);
}

// ---------------------------------------------------------------------------
// Decode attention (round-6 best). One block per (b,h): 512 blocks, 8 warps,
// 2-row unroll, streaming loads.
// ---------------------------------------------------------------------------
__global__ void __launch_bounds__(256) decode_attn(const float* __restrict__ kc,
                                                   const float* __restrict__ vc) {
    int bh   = blockIdx.x;
    int b    = bh >> 5;
    int h    = bh & 31;
    int tid  = threadIdx.x;
    int w    = tid >> 5;
    int lane = tid & 31;

    const float4* K = reinterpret_cast<const float4*>(kc + (size_t)bh * SEQ * HD);
    const float4* V = reinterpret_cast<const float4*>(vc + (size_t)bh * SEQ * HD);

    float4 q4 = reinterpret_cast<const float4*>(g_q + b * DIM + h * HD)[lane];
    const float scale = 0.08838834764831845f;   // 1/sqrt(128)

    float  m = -INFINITY;
    float  l = 0.f;
    float4 o = make_float4(0.f, 0.f, 0.f, 0.f);

    for (int i = 0; i < SEQ / 16; i++) {
        int r1 = i * 16 + w;
        int r2 = r1 + 8;
        float4 k1 = __ldcs(K + (size_t)r1 * (HD / 4) + lane);
        float4 v1 = __ldcs(V + (size_t)r1 * (HD / 4) + lane);
        float4 k2 = __ldcs(K + (size_t)r2 * (HD / 4) + lane);
        float4 v2 = __ldcs(V + (size_t)r2 * (HD / 4) + lane);

        float s1 = q4.x * k1.x + q4.y * k1.y + q4.z * k1.z + q4.w * k1.w;
        float s2 = q4.x * k2.x + q4.y * k2.y + q4.z * k2.z + q4.w * k2.w;
#pragma unroll
        for (int off = 16; off; off >>= 1) {
            s1 += __shfl_xor_sync(0xffffffffu, s1, off);
            s2 += __shfl_xor_sync(0xffffffffu, s2, off);
        }
        s1 *= scale;
        s2 *= scale;

        float nm = fmaxf(m, fmaxf(s1, s2));
        float c  = __expf(m - nm);
        float p1 = __expf(s1 - nm);
        float p2 = __expf(s2 - nm);
        l   = l * c + p1 + p2;
        o.x = o.x * c + p1 * v1.x + p2 * v2.x;
        o.y = o.y * c + p1 * v1.y + p2 * v2.y;
        o.z = o.z * c + p1 * v1.z + p2 * v2.z;
        o.w = o.w * c + p1 * v1.w + p2 * v2.w;
        m   = nm;
    }

    // new token (row 4096) handled by warp 0
    if (w == 0) {
        const float4* Kn = reinterpret_cast<const float4*>(g_kn + b * DIM + h * HD);
        const float4* Vn = reinterpret_cast<const float4*>(g_vn + b * DIM + h * HD);
        float4 kv = Kn[lane];
        float4 vv = Vn[lane];
        float s = q4.x * kv.x + q4.y * kv.y + q4.z * kv.z + q4.w * kv.w;
#pragma unroll
        for (int off = 16; off; off >>= 1)
            s += __shfl_xor_sync(0xffffffffu, s, off);
        s *= scale;
        float nm = fmaxf(m, s);
        float c  = __expf(m - nm);
        float p  = __expf(s - nm);
        l   = l * c + p;
        o.x = o.x * c + p * vv.x;
        o.y = o.y * c + p * vv.y;
        o.z = o.z * c + p * vv.z;
        o.w = o.w * c + p * vv.w;
        m   = nm;
    }

    // merge 8 warp-partials
    __shared__ float  sm[8];
    __shared__ float  sl[8];
    __shared__ float4 so[8][32];
    so[w][lane] = o;
    if (lane == 0) { sm[w] = m; sl[w] = l; }
    __syncthreads();

    if (tid < HD) {
        int d = tid;
        float gm = sm[0];
#pragma unroll
        for (int i = 1; i < 8; i++) gm = fmaxf(gm, sm[i]);
        const float* sof = reinterpret_cast<const float*>(so);
        float num = 0.f, den = 0.f;
#pragma unroll
        for (int i = 0; i < 8; i++) {
            float f = __expf(sm[i] - gm);
            num += f * sof[i * HD + d];
            den += f * sl[i];
        }
        g_att[b * DIM + h * HD + d] = num / den;
    }
}

// ---------------------------------------------------------------------------
extern "C" void kernel_launch(void* const* d_in, const int* in_sizes, int n_in,
                              void* d_out, int out_size) {
    const float* x  = (const float*)d_in[0];
    const float* kc = (const float*)d_in[1];
    const float* vc = (const float*)d_in[2];
    const float* wq = (const float*)d_in[3];
    const float* wk = (const float*)d_in[4];
    const float* wv = (const float*)d_in[5];
    const float* wo = (const float*)d_in[6];
    float* out = (float*)d_out;

    qkv_gemm  <<<3 * DIM / BROWS, 256>>>(x, wq, wk, wv);
    decode_attn<<<BATCH * NH, 256>>>(kc, vc);
    oproj_gemm<<<DIM / BROWS, 256>>>(wo, out);
}

// round 11
// speedup vs baseline: 1.4473x; 1.2187x over previous
#include <cuda_runtime.h>
#include <math.h>
#include <stdint.h>

#define DIM   4096
#define NH    32
#define HD    128
#define SEQ   4096
#define BATCH 16

typedef unsigned long long u64;

// Scratch (allocation-free)
__device__ float g_q  [BATCH * DIM];
__device__ float g_kn [BATCH * DIM];
__device__ float g_vn [BATCH * DIM];
__device__ float g_att[BATCH * DIM];

// ---------------- packed fp32x2 helpers ----------------
__device__ __forceinline__ u64 ffma2(u64 a, u64 b, u64 c) {
    u64 d; asm("fma.rn.f32x2 %0, %1, %2, %3;" : "=l"(d) : "l"(a), "l"(b), "l"(c)); return d;
}
__device__ __forceinline__ void unpack2(u64 v, float& lo, float& hi) {
    asm("mov.b64 {%0, %1}, %2;" : "=f"(lo), "=f"(hi) : "l"(v));
}
__device__ __forceinline__ void cp_async16(uint32_t dst, const void* src) {
    asm volatile("cp.async.cg.shared.global [%0], [%1], 16;" :: "r"(dst), "l"(src));
}

#define ROW_U2 (DIM / 4)   // ulonglong2 (16B) elements per 4096-float row
#define KCH    128         // k floats per stage
#define GSTG   3           // smem stages per warp

// ---------------------------------------------------------------------------
// Skinny GEMM, barrier-free per-warp cp.async pipeline.
// Block: 8 warps x 4 unique W rows = 32 rows, 8 batches (batch half chosen by
// block). Each warp stages its own W rows into a private smem slice:
// sW[warp][stage][4][128], 3 stages, prefetch distance 2.
// A commit_group is issued EVERY iteration (empty at the tail) so that
// wait_group 1 at iteration kb always guarantees kb's stage has landed.
// No __syncthreads in the mainloop. x is read via LDG (L2-resident).
// ---------------------------------------------------------------------------
__device__ __forceinline__ void gemm_block(const float* __restrict__ x,
                                           const float* __restrict__ Wblk, // 32 rows
                                           float* __restrict__ out,
                                           int j0, int bg /* 0 or 8 */) {
    __shared__ float sW[8][GSTG][4][KCH];   // 48 KB

    int tid  = threadIdx.x;
    int w    = tid >> 5;
    int lane = tid & 31;

    const float* Wrows = Wblk + (size_t)(w * 4) * DIM;   // this warp's 4 rows
    const ulonglong2* X2 = reinterpret_cast<const ulonglong2*>(x);

    u64 acc[4][8];
#pragma unroll
    for (int r = 0; r < 4; r++)
#pragma unroll
        for (int b = 0; b < 8; b++) acc[r][b] = 0ull;

    // per-warp stage fill: 4 rows x 128 floats = 2KB = 4 x 16B per lane
    auto fill_stage = [&](int s, int kb) {
#pragma unroll
        for (int r = 0; r < 4; r++) {
            uint32_t dst = (uint32_t)__cvta_generic_to_shared(&sW[w][s][r][lane * 4]);
            cp_async16(dst, Wrows + (size_t)r * DIM + kb * KCH + lane * 4);
        }
    };

    // prologue: 2 stages in flight (one commit each)
    fill_stage(0, 0);
    asm volatile("cp.async.commit_group;");
    fill_stage(1, 1);
    asm volatile("cp.async.commit_group;");

    int s = 0;
#pragma unroll 1
    for (int kb = 0; kb < DIM / KCH; kb++) {
        // x loads first: independent of smem, fly during the wait
        ulonglong2 xv[8];
#pragma unroll
        for (int b = 0; b < 8; b++)
            xv[b] = X2[(size_t)(bg + b) * ROW_U2 + kb * 32 + lane];

        asm volatile("cp.async.wait_group 1;");
        __syncwarp();

        ulonglong2 wv[4];
#pragma unroll
        for (int r = 0; r < 4; r++)
            wv[r] = *reinterpret_cast<const ulonglong2*>(&sW[w][s][r][lane * 4]);

#pragma unroll
        for (int b = 0; b < 8; b++) {
#pragma unroll
            for (int r = 0; r < 4; r++) {
                acc[r][b] = ffma2(wv[r].x, xv[b].x, acc[r][b]);
                acc[r][b] = ffma2(wv[r].y, xv[b].y, acc[r][b]);
            }
        }

        // refill the slot two ahead; ALWAYS commit (empty groups keep the
        // wait_group accounting uniform through the drain)
        if (kb + 2 < DIM / KCH) {
            int ns = s + 2; if (ns >= GSTG) ns -= GSTG;
            fill_stage(ns, kb + 2);
        }
        asm volatile("cp.async.commit_group;");

        if (++s == GSTG) s = 0;
    }

    // collapse k-pairs, butterfly over lanes, lane0 writes
#pragma unroll
    for (int r = 0; r < 4; r++)
#pragma unroll
        for (int b = 0; b < 8; b++) {
            float lo, hi;
            unpack2(acc[r][b], lo, hi);
            float v = lo + hi;
#pragma unroll
            for (int off = 16; off; off >>= 1)
                v += __shfl_xor_sync(0xffffffffu, v, off);
            if (lane == 0)
                out[(size_t)(bg + b) * DIM + j0 + w * 4 + r] = v;
        }
}

// QKV: 768 blocks x 256 threads. blockIdx: row-block (32 rows) x batch-half.
__global__ void __launch_bounds__(256, 2) qkv_gemm(const float* __restrict__ x,
                                                   const float* __restrict__ wq,
                                                   const float* __restrict__ wk,
                                                   const float* __restrict__ wv) {
    int jg    = (blockIdx.x >> 1) * 32;       // fused row base
    int bg    = (blockIdx.x & 1) * 8;
    int which = jg >> 12;
    int jl    = jg & (DIM - 1);
    const float* W   = (which == 0) ? wq  : (which == 1) ? wk   : wv;
    float*       out = (which == 0) ? g_q : (which == 1) ? g_kn : g_vn;
    gemm_block(x, W + (size_t)jl * DIM, out, jl, bg);
}

// O projection: 256 blocks x 256 threads.
__global__ void __launch_bounds__(256, 2) oproj_gemm(const float* __restrict__ wo,
                                                     float* __restrict__ out) {
    int j  = (blockIdx.x >> 1) * 32;
    int bg = (blockIdx.x & 1) * 8;
    gemm_block(g_att, wo + (size_t)j * DIM, out, j, bg);
}

// ---------------------------------------------------------------------------
// Decode attention: one block per (b,h), 8 warps, 4-row unroll (no split).
// Warp w handles rows r, r+8, r+16, r+24 stepping 32 -> 8 LDG.128 in flight.
// ---------------------------------------------------------------------------
__global__ void __launch_bounds__(256) decode_attn(const float* __restrict__ kc,
                                                   const float* __restrict__ vc) {
    int bh   = blockIdx.x;
    int b    = bh >> 5;
    int h    = bh & 31;
    int tid  = threadIdx.x;
    int w    = tid >> 5;
    int lane = tid & 31;

    const float4* K = reinterpret_cast<const float4*>(kc + (size_t)bh * SEQ * HD);
    const float4* V = reinterpret_cast<const float4*>(vc + (size_t)bh * SEQ * HD);

    float4 q4 = reinterpret_cast<const float4*>(g_q + b * DIM + h * HD)[lane];
    const float scale = 0.08838834764831845f;   // 1/sqrt(128)

    float  m = -INFINITY;
    float  l = 0.f;
    float4 o = make_float4(0.f, 0.f, 0.f, 0.f);

    for (int i = 0; i < SEQ / 32; i++) {
        int r0 = i * 32 + w;
        float4 k0 = __ldcs(K + (size_t)(r0     ) * (HD / 4) + lane);
        float4 k1 = __ldcs(K + (size_t)(r0 +  8) * (HD / 4) + lane);
        float4 k2 = __ldcs(K + (size_t)(r0 + 16) * (HD / 4) + lane);
        float4 k3 = __ldcs(K + (size_t)(r0 + 24) * (HD / 4) + lane);
        float4 v0 = __ldcs(V + (size_t)(r0     ) * (HD / 4) + lane);
        float4 v1 = __ldcs(V + (size_t)(r0 +  8) * (HD / 4) + lane);
        float4 v2 = __ldcs(V + (size_t)(r0 + 16) * (HD / 4) + lane);
        float4 v3 = __ldcs(V + (size_t)(r0 + 24) * (HD / 4) + lane);

        float s0 = q4.x * k0.x + q4.y * k0.y + q4.z * k0.z + q4.w * k0.w;
        float s1 = q4.x * k1.x + q4.y * k1.y + q4.z * k1.z + q4.w * k1.w;
        float s2 = q4.x * k2.x + q4.y * k2.y + q4.z * k2.z + q4.w * k2.w;
        float s3 = q4.x * k3.x + q4.y * k3.y + q4.z * k3.z + q4.w * k3.w;
#pragma unroll
        for (int off = 16; off; off >>= 1) {
            s0 += __shfl_xor_sync(0xffffffffu, s0, off);
            s1 += __shfl_xor_sync(0xffffffffu, s1, off);
            s2 += __shfl_xor_sync(0xffffffffu, s2, off);
            s3 += __shfl_xor_sync(0xffffffffu, s3, off);
        }
        s0 *= scale; s1 *= scale; s2 *= scale; s3 *= scale;

        float nm = fmaxf(fmaxf(m, fmaxf(s0, s1)), fmaxf(s2, s3));
        float c  = __expf(m - nm);
        float p0 = __expf(s0 - nm);
        float p1 = __expf(s1 - nm);
        float p2 = __expf(s2 - nm);
        float p3 = __expf(s3 - nm);
        l   = l * c + p0 + p1 + p2 + p3;
        o.x = o.x * c + p0 * v0.x + p1 * v1.x + p2 * v2.x + p3 * v3.x;
        o.y = o.y * c + p0 * v0.y + p1 * v1.y + p2 * v2.y + p3 * v3.y;
        o.z = o.z * c + p0 * v0.z + p1 * v1.z + p2 * v2.z + p3 * v3.z;
        o.w = o.w * c + p0 * v0.w + p1 * v1.w + p2 * v2.w + p3 * v3.w;
        m   = nm;
    }

    // new token (row 4096) handled by warp 0
    if (w == 0) {
        const float4* Kn = reinterpret_cast<const float4*>(g_kn + b * DIM + h * HD);
        const float4* Vn = reinterpret_cast<const float4*>(g_vn + b * DIM + h * HD);
        float4 kv = Kn[lane];
        float4 vv = Vn[lane];
        float s = q4.x * kv.x + q4.y * kv.y + q4.z * kv.z + q4.w * kv.w;
#pragma unroll
        for (int off = 16; off; off >>= 1)
            s += __shfl_xor_sync(0xffffffffu, s, off);
        s *= scale;
        float nm = fmaxf(m, s);
        float c  = __expf(m - nm);
        float p  = __expf(s - nm);
        l   = l * c + p;
        o.x = o.x * c + p * vv.x;
        o.y = o.y * c + p * vv.y;
        o.z = o.z * c + p * vv.z;
        o.w = o.w * c + p * vv.w;
        m   = nm;
    }

    // merge 8 warp-partials
    __shared__ float  sm[8];
    __shared__ float  sl[8];
    __shared__ float4 so[8][32];
    so[w][lane] = o;
    if (lane == 0) { sm[w] = m; sl[w] = l; }
    __syncthreads();

    if (tid < HD) {
        int d = tid;
        float gm = sm[0];
#pragma unroll
        for (int i = 1; i < 8; i++) gm = fmaxf(gm, sm[i]);
        const float* sof = reinterpret_cast<const float*>(so);
        float num = 0.f, den = 0.f;
#pragma unroll
        for (int i = 0; i < 8; i++) {
            float f = __expf(sm[i] - gm);
            num += f * sof[i * HD + d];
            den += f * sl[i];
        }
        g_att[b * DIM + h * HD + d] = num / den;
    }
}

// ---------------------------------------------------------------------------
extern "C" void kernel_launch(void* const* d_in, const int* in_sizes, int n_in,
                              void* d_out, int out_size) {
    const float* x  = (const float*)d_in[0];
    const float* kc = (const float*)d_in[1];
    const float* vc = (const float*)d_in[2];
    const float* wq = (const float*)d_in[3];
    const float* wk = (const float*)d_in[4];
    const float* wv = (const float*)d_in[5];
    const float* wo = (const float*)d_in[6];
    float* out = (float*)d_out;

    qkv_gemm  <<<(3 * DIM / 32) * 2, 256>>>(x, wq, wk, wv);
    decode_attn<<<BATCH * NH, 256>>>(kc, vc);
    oproj_gemm<<<(DIM / 32) * 2, 256>>>(wo, out);
}